// round 16
// baseline (speedup 1.0000x reference)
#include <cuda_runtime.h>
#include <cuda_bf16.h>
#include <math.h>

#define BATCH 1024
#define DIM   4096
#define MAXR  19

// ---------------- scratch (no allocations allowed) ----------------
__device__ float    g_gradx[BATCH * DIM];
__device__ float    g_grady[BATCH * DIM];
__device__ float    g_y[BATCH * DIM];
__device__ int      g_idx[BATCH * MAXR];
__device__ int      g_radius[BATCH];
__device__ unsigned g_stepkeys[2 * MAXR];
__device__ unsigned g_kacc[2];

// ---------------- Threefry-2x32 (20 rounds), exactly as JAX ----------------
__device__ __forceinline__ unsigned rotl32(unsigned v, int r) {
    return (v << r) | (v >> (32 - r));
}

__device__ __forceinline__ void threefry2x32(unsigned k0, unsigned k1,
                                             unsigned x0, unsigned x1,
                                             unsigned& o0, unsigned& o1) {
    unsigned ks2 = k0 ^ k1 ^ 0x1BD11BDAu;
    x0 += k0; x1 += k1;
#define TF_RND(r) { x0 += x1; x1 = rotl32(x1, r); x1 ^= x0; }
    TF_RND(13) TF_RND(15) TF_RND(26) TF_RND(6)
    x0 += k1; x1 += ks2 + 1u;
    TF_RND(17) TF_RND(29) TF_RND(16) TF_RND(24)
    x0 += ks2; x1 += k0 + 2u;
    TF_RND(13) TF_RND(15) TF_RND(26) TF_RND(6)
    x0 += k0; x1 += k1 + 3u;
    TF_RND(17) TF_RND(29) TF_RND(16) TF_RND(24)
    x0 += k1; x1 += ks2 + 4u;
    TF_RND(13) TF_RND(15) TF_RND(26) TF_RND(6)
    x0 += ks2; x1 += k0 + 5u;
#undef TF_RND
    o0 = x0; o1 = x1;
}

// partitionable random_bits word for flat index i: o0 ^ o1 of threefry(key,(0,i))
__device__ __forceinline__ unsigned tf_bits(unsigned k0, unsigned k1, unsigned i) {
    unsigned o0, o1;
    threefry2x32(k0, k1, 0u, i, o0, o1);
    return o0 ^ o1;
}

__device__ __forceinline__ float u01_from_bits(unsigned bits) {
    return __uint_as_float((bits >> 9) | 0x3f800000u) - 1.0f;
}

__device__ __forceinline__ float gumbel_from_bits(unsigned bits) {
    const float tiny = 1.17549435e-38f;
    float u = u01_from_bits(bits) + tiny;
    return -logf(-logf(u));
}

// ---------------- kernel A: keys + radii (split-key randint, R15-confirmed) ----------
__global__ void init_rng_kernel() {
    __shared__ unsigned s_kr1[2], s_kr2[2];
    int tid = threadIdx.x;
    if (tid == 0) {
        // foldlike split(key42, 3): keys[i] = threefry(key42, (0,i))
        unsigned r0, r1, s0, s1, a0, a1;
        threefry2x32(0u, 42u, 0u, 0u, r0, r1);  // k_rad
        threefry2x32(0u, 42u, 0u, 1u, s0, s1);  // k_steps
        threefry2x32(0u, 42u, 0u, 2u, a0, a1);  // k_acc
        g_kacc[0] = a0; g_kacc[1] = a1;
        // randint's internal split(k_rad, 2)
        unsigned p0, p1, q0, q1;
        threefry2x32(r0, r1, 0u, 0u, p0, p1);
        threefry2x32(r0, r1, 0u, 1u, q0, q1);
        s_kr1[0] = p0; s_kr1[1] = p1;
        s_kr2[0] = q0; s_kr2[1] = q1;
        // step_keys = split(k_steps, 19)
        for (int t = 0; t < MAXR; t++) {
            unsigned o0, o1;
            threefry2x32(s0, s1, 0u, (unsigned)t, o0, o1);
            g_stepkeys[2 * t]     = o0;
            g_stepkeys[2 * t + 1] = o1;
        }
    }
    __syncthreads();
    // radius: hi = bits(k1, b), lo = bits(k2, b); mult = (2^16 % 19)^2 % 19 = 6
    for (int b = tid; b < BATCH; b += blockDim.x) {
        unsigned hi = tf_bits(s_kr1[0], s_kr1[1], (unsigned)b);
        unsigned lo = tf_bits(s_kr2[0], s_kr2[1], (unsigned)b);
        unsigned off = ((hi % 19u) * 6u + (lo % 19u)) % 19u;
        g_radius[b] = 1 + (int)off;
    }
}

// ---------------- fp32 SGEMM: C[M,4096] = A[M,4096] @ W[4096,4096] + bias ----------------
__global__ __launch_bounds__(256) void sgemm_bias(const float* __restrict__ A,
                                                  const float* __restrict__ W,
                                                  const float* __restrict__ bias,
                                                  float* __restrict__ C) {
    __shared__ float As[8][128];
    __shared__ float Bs[8][128];
    int bx = blockIdx.x;   // N tile (32)
    int by = blockIdx.y;   // M tile (8)
    int tid = threadIdx.x;
    int tr = tid >> 4, tc = tid & 15;

    float acc[8][8];
#pragma unroll
    for (int i = 0; i < 8; i++)
#pragma unroll
        for (int j = 0; j < 8; j++) acc[i][j] = 0.0f;

    int aRow = tid >> 1, aK4 = (tid & 1) * 4;
    int bRow = tid >> 5, bC4 = (tid & 31) * 4;
    const float* Ab = A + (by * 128 + aRow) * DIM + aK4;
    const float* Wb = W + bRow * DIM + bx * 128 + bC4;

    for (int k0 = 0; k0 < DIM; k0 += 8) {
        float4 a4 = *(const float4*)(Ab + k0);
        As[aK4 + 0][aRow] = a4.x;
        As[aK4 + 1][aRow] = a4.y;
        As[aK4 + 2][aRow] = a4.z;
        As[aK4 + 3][aRow] = a4.w;
        float4 b4 = *(const float4*)(Wb + (size_t)k0 * DIM);
        *(float4*)&Bs[bRow][bC4] = b4;
        __syncthreads();
#pragma unroll
        for (int k = 0; k < 8; k++) {
            float ra[8], rb[8];
#pragma unroll
            for (int i = 0; i < 8; i++) ra[i] = As[k][tr * 8 + i];
#pragma unroll
            for (int j = 0; j < 8; j++) rb[j] = Bs[k][tc * 8 + j];
#pragma unroll
            for (int i = 0; i < 8; i++)
#pragma unroll
                for (int j = 0; j < 8; j++) acc[i][j] += ra[i] * rb[j];
        }
        __syncthreads();
    }
#pragma unroll
    for (int i = 0; i < 8; i++) {
        int gm = by * 128 + tr * 8 + i;
#pragma unroll
        for (int j = 0; j < 8; j += 4) {
            int gn = bx * 128 + tc * 8 + j;
            float4 bv = *(const float4*)(bias + gn);
            float4 o;
            o.x = acc[i][j + 0] + bv.x;
            o.y = acc[i][j + 1] + bv.y;
            o.z = acc[i][j + 2] + bv.z;
            o.w = acc[i][j + 3] + bv.w;
            *(float4*)(C + (size_t)gm * DIM + gn) = o;
        }
    }
}

// ---------------- sampler: one block per row ----------------
__global__ __launch_bounds__(256) void sampler_kernel(const float* __restrict__ x) {
    int row = blockIdx.x;
    int tid = threadIdx.x;
    __shared__ unsigned xb[128];
    __shared__ float rv[256];
    __shared__ int   ri[256];
    __shared__ unsigned skeys[2 * MAXR];

    if (tid < 128) {
        unsigned w = 0;
        const float* xr = x + (size_t)row * DIM + tid * 32;
#pragma unroll
        for (int k = 0; k < 32; k++) w |= (xr[k] != 0.0f ? 1u : 0u) << k;
        xb[tid] = w;
    }
    if (tid < 2 * MAXR) skeys[tid] = g_stepkeys[tid];

    int rad = g_radius[row];
    float gx[16];
    const float* gr = g_gradx + (size_t)row * DIM + tid * 16;
#pragma unroll
    for (int k = 0; k < 16; k += 4) {
        float4 v = *(const float4*)(gr + k);
        gx[k] = v.x; gx[k + 1] = v.y; gx[k + 2] = v.z; gx[k + 3] = v.w;
    }
    __syncthreads();

    unsigned base_cnt = (unsigned)(row * DIM);
    for (int t = 0; t < rad; t++) {
        unsigned k0 = skeys[2 * t], k1 = skeys[2 * t + 1];
        float best = -1e30f; int bi = 0;
#pragma unroll
        for (int k = 0; k < 16; k++) {
            int d = tid * 16 + k;
            float g = gumbel_from_bits(tf_bits(k0, k1, base_cnt + (unsigned)d));
            float dlt = ((xb[d >> 5] >> (d & 31)) & 1u) ? -1.0f : 1.0f;
            float v = __fadd_rn(g, __fmul_rn(__fmul_rn(dlt, gx[k]), 0.5f));
            if (v > best) { best = v; bi = d; }
        }
        rv[tid] = best; ri[tid] = bi;
        __syncthreads();
        for (int s = 128; s; s >>= 1) {
            if (tid < s) {
                float v2 = rv[tid + s]; int i2 = ri[tid + s];
                if (v2 > rv[tid] || (v2 == rv[tid] && i2 < ri[tid])) {
                    rv[tid] = v2; ri[tid] = i2;
                }
            }
            __syncthreads();
        }
        if (tid == 0) {
            int i = ri[0];
            g_idx[row * MAXR + t] = i;
            xb[i >> 5] ^= (1u << (i & 31));
        }
        __syncthreads();
    }
#pragma unroll
    for (int k = 0; k < 16; k++) {
        int d = tid * 16 + k;
        g_y[(size_t)row * DIM + d] = (float)((xb[d >> 5] >> (d & 31)) & 1u);
    }
}

// ---------------- finalize: scores, trajectory logprobs, accept, output ----------------
__device__ __forceinline__ float blk_reduce(float v, float* red, int tid) {
    red[tid] = v; __syncthreads();
    for (int s = 128; s; s >>= 1) {
        if (tid < s) red[tid] += red[tid + s];
        __syncthreads();
    }
    float r = red[0]; __syncthreads();
    return r;
}

__global__ __launch_bounds__(256) void finalize_kernel(const float* __restrict__ x,
                                                       const float* __restrict__ bvec,
                                                       float* __restrict__ out) {
    int row = blockIdx.x;
    int tid = threadIdx.x;
    __shared__ unsigned xb[128], yb[128];
    __shared__ float red[256];
    __shared__ int accept_s;

    const float* xr  = x        + (size_t)row * DIM;
    const float* yr  = g_y      + (size_t)row * DIM;
    const float* gxr = g_gradx  + (size_t)row * DIM;
    const float* gyr = g_grady  + (size_t)row * DIM;

    float Sx = 0.f, Sy = 0.f, dxg = 0.f, dxb = 0.f, dyg = 0.f, dyb = 0.f;
#pragma unroll 4
    for (int k = 0; k < 16; k++) {
        int d = tid + 256 * k;
        float xd = xr[d], yd = yr[d], gxd = gxr[d], gyd = gyr[d], bd = bvec[d];
        float dltx = 1.0f - 2.0f * xd;
        float dlty = 1.0f - 2.0f * yd;
        Sx += expf(dltx * (0.5f * gxd));
        Sy += expf(dlty * (0.5f * gyd));
        dxg += xd * gxd; dxb += xd * bd;
        dyg += yd * gyd; dyb += yd * bd;
    }
    if (tid < 128) {
        unsigned w = 0;
        const float* p = xr + tid * 32;
#pragma unroll
        for (int k = 0; k < 32; k++) w |= (p[k] != 0.0f ? 1u : 0u) << k;
        xb[tid] = w;
    } else {
        unsigned w = 0;
        const float* p = yr + (tid - 128) * 32;
#pragma unroll
        for (int k = 0; k < 32; k++) w |= (p[k] != 0.0f ? 1u : 0u) << k;
        yb[tid - 128] = w;
    }
    __syncthreads();

    Sx  = blk_reduce(Sx, red, tid);
    Sy  = blk_reduce(Sy, red, tid);
    dxg = blk_reduce(dxg, red, tid);
    dxb = blk_reduce(dxb, red, tid);
    dyg = blk_reduce(dyg, red, tid);
    dyb = blk_reduce(dyb, red, tid);

    if (tid == 0) {
        int rad = g_radius[row];
        // forward: states 0..rad-1 under grad_x
        float accf = 0.0f, S = Sx;
        for (int t = 0; t < rad; t++) {
            int i = g_idx[row * MAXR + t];
            float dlt = ((xb[i >> 5] >> (i & 31)) & 1u) ? -1.0f : 1.0f;
            float s = 0.5f * gxr[i];
            accf += dlt * s - logf(S);
            S += expf(-dlt * s) - expf(dlt * s);
            xb[i >> 5] ^= (1u << (i & 31));
        }
        // backward: states rad..1 under grad_y, walking back from y (= state_rad)
        float accb = 0.0f; S = Sy;
        for (int t = rad - 1; t >= 0; t--) {
            int i = g_idx[row * MAXR + t];
            float dlt = ((yb[i >> 5] >> (i & 31)) & 1u) ? -1.0f : 1.0f;
            float s = 0.5f * gyr[i];
            accb += dlt * s - logf(S);
            if (t > 0) {
                S += expf(-dlt * s) - expf(dlt * s);
                yb[i >> 5] ^= (1u << (i & 31));
            }
        }
        float score_x = 0.5f * dxg + 0.5f * dxb;
        float score_y = 0.5f * dyg + 0.5f * dyb;
        float log_acc = (accb + score_y) - (accf + score_x);
        float u = u01_from_bits(tf_bits(g_kacc[0], g_kacc[1], (unsigned)row));
        accept_s = (expf(log_acc) >= u) ? 1 : 0;
    }
    __syncthreads();

    int acc = accept_s;
#pragma unroll
    for (int k = 0; k < 4; k++) {
        int d4 = (tid + 256 * k) * 4;
        float4 yv = *(const float4*)(yr + d4);
        float4 xv = *(const float4*)(xr + d4);
        *(float4*)(out + (size_t)row * DIM + d4) = acc ? yv : xv;
    }
}

// ---------------- launch ----------------
extern "C" void kernel_launch(void* const* d_in, const int* in_sizes, int n_in,
                              void* d_out, int out_size) {
    const float* x  = (const float*)d_in[0];
    const float* W  = (const float*)d_in[1];
    const float* bb = (const float*)d_in[2];
    float* out = (float*)d_out;

    float *gx, *gy, *yy;
    cudaGetSymbolAddress((void**)&gx, g_gradx);
    cudaGetSymbolAddress((void**)&gy, g_grady);
    cudaGetSymbolAddress((void**)&yy, g_y);

    init_rng_kernel<<<1, 512>>>();
    sgemm_bias<<<dim3(32, 8), 256>>>(x, W, bb, gx);   // grad_x = x@W + b
    sampler_kernel<<<1024, 256>>>(x);                  // path sampling -> y, idx
    sgemm_bias<<<dim3(32, 8), 256>>>(yy, W, bb, gy);  // grad_y = y@W + b
    finalize_kernel<<<1024, 256>>>(x, bb, out);        // logprobs, accept, output
}

// round 17
// speedup vs baseline: 1.1621x; 1.1621x over previous
#include <cuda_runtime.h>
#include <cuda_bf16.h>
#include <math.h>

#define BATCH 1024
#define DIM   4096
#define MAXR  19
#define BK    16

// ---------------- scratch (no allocations allowed) ----------------
__device__ float    g_gradx[BATCH * DIM];
__device__ float    g_grady[BATCH * DIM];
__device__ float    g_y[BATCH * DIM];
__device__ int      g_idx[BATCH * MAXR];
__device__ int      g_radius[BATCH];
__device__ unsigned g_stepkeys[2 * MAXR];
__device__ unsigned g_kacc[2];

// ---------------- Threefry-2x32 (20 rounds), exactly as JAX ----------------
__device__ __forceinline__ unsigned rotl32(unsigned v, int r) {
    return (v << r) | (v >> (32 - r));
}

__device__ __forceinline__ void threefry2x32(unsigned k0, unsigned k1,
                                             unsigned x0, unsigned x1,
                                             unsigned& o0, unsigned& o1) {
    unsigned ks2 = k0 ^ k1 ^ 0x1BD11BDAu;
    x0 += k0; x1 += k1;
#define TF_RND(r) { x0 += x1; x1 = rotl32(x1, r); x1 ^= x0; }
    TF_RND(13) TF_RND(15) TF_RND(26) TF_RND(6)
    x0 += k1; x1 += ks2 + 1u;
    TF_RND(17) TF_RND(29) TF_RND(16) TF_RND(24)
    x0 += ks2; x1 += k0 + 2u;
    TF_RND(13) TF_RND(15) TF_RND(26) TF_RND(6)
    x0 += k0; x1 += k1 + 3u;
    TF_RND(17) TF_RND(29) TF_RND(16) TF_RND(24)
    x0 += k1; x1 += ks2 + 4u;
    TF_RND(13) TF_RND(15) TF_RND(26) TF_RND(6)
    x0 += ks2; x1 += k0 + 5u;
#undef TF_RND
    o0 = x0; o1 = x1;
}

__device__ __forceinline__ unsigned tf_bits(unsigned k0, unsigned k1, unsigned i) {
    unsigned o0, o1;
    threefry2x32(k0, k1, 0u, i, o0, o1);
    return o0 ^ o1;
}

__device__ __forceinline__ float u01_from_bits(unsigned bits) {
    return __uint_as_float((bits >> 9) | 0x3f800000u) - 1.0f;
}

__device__ __forceinline__ float gumbel_from_bits(unsigned bits) {
    const float tiny = 1.17549435e-38f;
    float u = u01_from_bits(bits) + tiny;
    return -logf(-logf(u));
}

// ---------------- kernel A: keys + radii (split-key randint, confirmed) ----------
__global__ void init_rng_kernel() {
    __shared__ unsigned s_kr1[2], s_kr2[2];
    int tid = threadIdx.x;
    if (tid == 0) {
        unsigned r0, r1, s0, s1, a0, a1;
        threefry2x32(0u, 42u, 0u, 0u, r0, r1);  // k_rad
        threefry2x32(0u, 42u, 0u, 1u, s0, s1);  // k_steps
        threefry2x32(0u, 42u, 0u, 2u, a0, a1);  // k_acc
        g_kacc[0] = a0; g_kacc[1] = a1;
        unsigned p0, p1, q0, q1;
        threefry2x32(r0, r1, 0u, 0u, p0, p1);   // split(k_rad,2)[0]
        threefry2x32(r0, r1, 0u, 1u, q0, q1);   // split(k_rad,2)[1]
        s_kr1[0] = p0; s_kr1[1] = p1;
        s_kr2[0] = q0; s_kr2[1] = q1;
        for (int t = 0; t < MAXR; t++) {
            unsigned o0, o1;
            threefry2x32(s0, s1, 0u, (unsigned)t, o0, o1);
            g_stepkeys[2 * t]     = o0;
            g_stepkeys[2 * t + 1] = o1;
        }
    }
    __syncthreads();
    for (int b = tid; b < BATCH; b += blockDim.x) {
        unsigned hi = tf_bits(s_kr1[0], s_kr1[1], (unsigned)b);
        unsigned lo = tf_bits(s_kr2[0], s_kr2[1], (unsigned)b);
        unsigned off = ((hi % 19u) * 6u + (lo % 19u)) % 19u;
        g_radius[b] = 1 + (int)off;
    }
}

// ---------------- fp32 SGEMM, double-buffered BK=16 ----------------
// Bit-identical accumulation sequence to the R16 kernel (same products,
// same per-thread k-ascending add order) -> grads unchanged bit-for-bit.
__global__ __launch_bounds__(256) void sgemm_bias(const float* __restrict__ A,
                                                  const float* __restrict__ W,
                                                  const float* __restrict__ bias,
                                                  float* __restrict__ C) {
    __shared__ float As[2][BK][132];   // padded: kills STS bank conflicts
    __shared__ float Bs[2][BK][128];

    int bx = blockIdx.x;   // N tile (32)
    int by = blockIdx.y;   // M tile (8)
    int tid = threadIdx.x;
    int tr = tid >> 4, tc = tid & 15;

    float acc[8][8];
#pragma unroll
    for (int i = 0; i < 8; i++)
#pragma unroll
        for (int j = 0; j < 8; j++) acc[i][j] = 0.0f;

    // A: 128 rows x 16 k per stage; 4 threads per row (float4 each)
    int ar = tid >> 2;                 // 0..63 ; +64 on second half
    int ak4 = (tid & 3) * 4;           // 0,4,8,12
    // B: 16 k-rows x 128 n per stage; 32 threads per k-row
    int bk = tid >> 5;                 // 0..7 ; +8 on second half
    int bn4 = (tid & 31) * 4;

    const float* Ab = A + (size_t)(by * 128) * DIM;
    const float* Wb = W + bx * 128;

    float4 a0, a1, b0, b1;

    // prefetch + store stage 0
    a0 = *(const float4*)(Ab + (size_t)ar * DIM + ak4);
    a1 = *(const float4*)(Ab + (size_t)(ar + 64) * DIM + ak4);
    b0 = *(const float4*)(Wb + (size_t)bk * DIM + bn4);
    b1 = *(const float4*)(Wb + (size_t)(bk + 8) * DIM + bn4);
    As[0][ak4 + 0][ar] = a0.x; As[0][ak4 + 1][ar] = a0.y;
    As[0][ak4 + 2][ar] = a0.z; As[0][ak4 + 3][ar] = a0.w;
    As[0][ak4 + 0][ar + 64] = a1.x; As[0][ak4 + 1][ar + 64] = a1.y;
    As[0][ak4 + 2][ar + 64] = a1.z; As[0][ak4 + 3][ar + 64] = a1.w;
    *(float4*)&Bs[0][bk][bn4]     = b0;
    *(float4*)&Bs[0][bk + 8][bn4] = b1;
    __syncthreads();

    int s = 0;
    for (int k0 = BK; k0 < DIM; k0 += BK) {
        // prefetch next tile into registers
        a0 = *(const float4*)(Ab + (size_t)ar * DIM + k0 + ak4);
        a1 = *(const float4*)(Ab + (size_t)(ar + 64) * DIM + k0 + ak4);
        b0 = *(const float4*)(Wb + (size_t)(k0 + bk) * DIM + bn4);
        b1 = *(const float4*)(Wb + (size_t)(k0 + bk + 8) * DIM + bn4);

        // compute current stage
#pragma unroll
        for (int k = 0; k < BK; k++) {
            float ra[8], rb[8];
            *(float4*)(ra)     = *(const float4*)&As[s][k][tr * 8];
            *(float4*)(ra + 4) = *(const float4*)&As[s][k][tr * 8 + 4];
            *(float4*)(rb)     = *(const float4*)&Bs[s][k][tc * 8];
            *(float4*)(rb + 4) = *(const float4*)&Bs[s][k][tc * 8 + 4];
#pragma unroll
            for (int i = 0; i < 8; i++)
#pragma unroll
                for (int j = 0; j < 8; j++) acc[i][j] += ra[i] * rb[j];
        }

        // store prefetched tile into the other stage
        int n = s ^ 1;
        As[n][ak4 + 0][ar] = a0.x; As[n][ak4 + 1][ar] = a0.y;
        As[n][ak4 + 2][ar] = a0.z; As[n][ak4 + 3][ar] = a0.w;
        As[n][ak4 + 0][ar + 64] = a1.x; As[n][ak4 + 1][ar + 64] = a1.y;
        As[n][ak4 + 2][ar + 64] = a1.z; As[n][ak4 + 3][ar + 64] = a1.w;
        *(float4*)&Bs[n][bk][bn4]     = b0;
        *(float4*)&Bs[n][bk + 8][bn4] = b1;
        __syncthreads();
        s = n;
    }

    // final stage compute
#pragma unroll
    for (int k = 0; k < BK; k++) {
        float ra[8], rb[8];
        *(float4*)(ra)     = *(const float4*)&As[s][k][tr * 8];
        *(float4*)(ra + 4) = *(const float4*)&As[s][k][tr * 8 + 4];
        *(float4*)(rb)     = *(const float4*)&Bs[s][k][tc * 8];
        *(float4*)(rb + 4) = *(const float4*)&Bs[s][k][tc * 8 + 4];
#pragma unroll
        for (int i = 0; i < 8; i++)
#pragma unroll
            for (int j = 0; j < 8; j++) acc[i][j] += ra[i] * rb[j];
    }

#pragma unroll
    for (int i = 0; i < 8; i++) {
        int gm = by * 128 + tr * 8 + i;
#pragma unroll
        for (int j = 0; j < 8; j += 4) {
            int gn = bx * 128 + tc * 8 + j;
            float4 bv = *(const float4*)(bias + gn);
            float4 o;
            o.x = acc[i][j + 0] + bv.x;
            o.y = acc[i][j + 1] + bv.y;
            o.z = acc[i][j + 2] + bv.z;
            o.w = acc[i][j + 3] + bv.w;
            *(float4*)(C + (size_t)gm * DIM + gn) = o;
        }
    }
}

// ---------------- sampler: one block per row ----------------
__global__ __launch_bounds__(256) void sampler_kernel(const float* __restrict__ x) {
    int row = blockIdx.x;
    int tid = threadIdx.x;
    __shared__ unsigned xb[128];
    __shared__ float rv[256];
    __shared__ int   ri[256];
    __shared__ unsigned skeys[2 * MAXR];

    if (tid < 128) {
        unsigned w = 0;
        const float* xr = x + (size_t)row * DIM + tid * 32;
#pragma unroll
        for (int k = 0; k < 32; k++) w |= (xr[k] != 0.0f ? 1u : 0u) << k;
        xb[tid] = w;
    }
    if (tid < 2 * MAXR) skeys[tid] = g_stepkeys[tid];

    int rad = g_radius[row];
    float gx[16];
    const float* gr = g_gradx + (size_t)row * DIM + tid * 16;
#pragma unroll
    for (int k = 0; k < 16; k += 4) {
        float4 v = *(const float4*)(gr + k);
        gx[k] = v.x; gx[k + 1] = v.y; gx[k + 2] = v.z; gx[k + 3] = v.w;
    }
    __syncthreads();

    unsigned base_cnt = (unsigned)(row * DIM);
    for (int t = 0; t < rad; t++) {
        unsigned k0 = skeys[2 * t], k1 = skeys[2 * t + 1];
        float best = -1e30f; int bi = 0;
#pragma unroll
        for (int k = 0; k < 16; k++) {
            int d = tid * 16 + k;
            float g = gumbel_from_bits(tf_bits(k0, k1, base_cnt + (unsigned)d));
            float dlt = ((xb[d >> 5] >> (d & 31)) & 1u) ? -1.0f : 1.0f;
            float v = __fadd_rn(g, __fmul_rn(__fmul_rn(dlt, gx[k]), 0.5f));
            if (v > best) { best = v; bi = d; }
        }
        rv[tid] = best; ri[tid] = bi;
        __syncthreads();
        for (int s = 128; s; s >>= 1) {
            if (tid < s) {
                float v2 = rv[tid + s]; int i2 = ri[tid + s];
                if (v2 > rv[tid] || (v2 == rv[tid] && i2 < ri[tid])) {
                    rv[tid] = v2; ri[tid] = i2;
                }
            }
            __syncthreads();
        }
        if (tid == 0) {
            int i = ri[0];
            g_idx[row * MAXR + t] = i;
            xb[i >> 5] ^= (1u << (i & 31));
        }
        __syncthreads();
    }
#pragma unroll
    for (int k = 0; k < 16; k++) {
        int d = tid * 16 + k;
        g_y[(size_t)row * DIM + d] = (float)((xb[d >> 5] >> (d & 31)) & 1u);
    }
}

// ---------------- finalize ----------------
__device__ __forceinline__ float blk_reduce(float v, float* red, int tid) {
    red[tid] = v; __syncthreads();
    for (int s = 128; s; s >>= 1) {
        if (tid < s) red[tid] += red[tid + s];
        __syncthreads();
    }
    float r = red[0]; __syncthreads();
    return r;
}

__global__ __launch_bounds__(256) void finalize_kernel(const float* __restrict__ x,
                                                       const float* __restrict__ bvec,
                                                       float* __restrict__ out) {
    int row = blockIdx.x;
    int tid = threadIdx.x;
    __shared__ unsigned xb[128], yb[128];
    __shared__ float red[256];
    __shared__ int accept_s;

    const float* xr  = x        + (size_t)row * DIM;
    const float* yr  = g_y      + (size_t)row * DIM;
    const float* gxr = g_gradx  + (size_t)row * DIM;
    const float* gyr = g_grady  + (size_t)row * DIM;

    float Sx = 0.f, Sy = 0.f, dxg = 0.f, dxb = 0.f, dyg = 0.f, dyb = 0.f;
#pragma unroll 4
    for (int k = 0; k < 16; k++) {
        int d = tid + 256 * k;
        float xd = xr[d], yd = yr[d], gxd = gxr[d], gyd = gyr[d], bd = bvec[d];
        float dltx = 1.0f - 2.0f * xd;
        float dlty = 1.0f - 2.0f * yd;
        Sx += expf(dltx * (0.5f * gxd));
        Sy += expf(dlty * (0.5f * gyd));
        dxg += xd * gxd; dxb += xd * bd;
        dyg += yd * gyd; dyb += yd * bd;
    }
    if (tid < 128) {
        unsigned w = 0;
        const float* p = xr + tid * 32;
#pragma unroll
        for (int k = 0; k < 32; k++) w |= (p[k] != 0.0f ? 1u : 0u) << k;
        xb[tid] = w;
    } else {
        unsigned w = 0;
        const float* p = yr + (tid - 128) * 32;
#pragma unroll
        for (int k = 0; k < 32; k++) w |= (p[k] != 0.0f ? 1u : 0u) << k;
        yb[tid - 128] = w;
    }
    __syncthreads();

    Sx  = blk_reduce(Sx, red, tid);
    Sy  = blk_reduce(Sy, red, tid);
    dxg = blk_reduce(dxg, red, tid);
    dxb = blk_reduce(dxb, red, tid);
    dyg = blk_reduce(dyg, red, tid);
    dyb = blk_reduce(dyb, red, tid);

    if (tid == 0) {
        int rad = g_radius[row];
        float accf = 0.0f, S = Sx;
        for (int t = 0; t < rad; t++) {
            int i = g_idx[row * MAXR + t];
            float dlt = ((xb[i >> 5] >> (i & 31)) & 1u) ? -1.0f : 1.0f;
            float s = 0.5f * gxr[i];
            accf += dlt * s - logf(S);
            S += expf(-dlt * s) - expf(dlt * s);
            xb[i >> 5] ^= (1u << (i & 31));
        }
        float accb = 0.0f; S = Sy;
        for (int t = rad - 1; t >= 0; t--) {
            int i = g_idx[row * MAXR + t];
            float dlt = ((yb[i >> 5] >> (i & 31)) & 1u) ? -1.0f : 1.0f;
            float s = 0.5f * gyr[i];
            accb += dlt * s - logf(S);
            if (t > 0) {
                S += expf(-dlt * s) - expf(dlt * s);
                yb[i >> 5] ^= (1u << (i & 31));
            }
        }
        float score_x = 0.5f * dxg + 0.5f * dxb;
        float score_y = 0.5f * dyg + 0.5f * dyb;
        float log_acc = (accb + score_y) - (accf + score_x);
        float u = u01_from_bits(tf_bits(g_kacc[0], g_kacc[1], (unsigned)row));
        accept_s = (expf(log_acc) >= u) ? 1 : 0;
    }
    __syncthreads();

    int acc = accept_s;
#pragma unroll
    for (int k = 0; k < 4; k++) {
        int d4 = (tid + 256 * k) * 4;
        float4 yv = *(const float4*)(yr + d4);
        float4 xv = *(const float4*)(xr + d4);
        *(float4*)(out + (size_t)row * DIM + d4) = acc ? yv : xv;
    }
}

// ---------------- launch ----------------
extern "C" void kernel_launch(void* const* d_in, const int* in_sizes, int n_in,
                              void* d_out, int out_size) {
    const float* x  = (const float*)d_in[0];
    const float* W  = (const float*)d_in[1];
    const float* bb = (const float*)d_in[2];
    float* out = (float*)d_out;

    float *gx, *gy, *yy;
    cudaGetSymbolAddress((void**)&gx, g_gradx);
    cudaGetSymbolAddress((void**)&gy, g_grady);
    cudaGetSymbolAddress((void**)&yy, g_y);

    init_rng_kernel<<<1, 512>>>();
    sgemm_bias<<<dim3(32, 8), 256>>>(x, W, bb, gx);   // grad_x = x@W + b
    sampler_kernel<<<1024, 256>>>(x);                  // path sampling -> y, idx
    sgemm_bias<<<dim3(32, 8), 256>>>(yy, W, bb, gy);  // grad_y = y@W + b
    finalize_kernel<<<1024, 256>>>(x, bb, out);        // logprobs, accept, output
}